// round 3
// baseline (speedup 1.0000x reference)
#include <cuda_runtime.h>
#include <math.h>

// Problem: B=128, OUT=1024, IN=1024
// d_in order (metadata): 0=input(128*1024) 1=weight(1024*1024) 2=bias(1024)
//                        3=x0 4=dx 5=a 6=d  (all 1024*1024 except bias)
// out: (128,1024) float32
//
// res = mu + eps*sigma + bias with eps=(Yb-mu)/sigma collapses to Yb + bias,
// where Yb = count of Bernoulli successes under JAX partitionable threefry.

#define B_DIM   128
#define OUT_DIM 1024
#define IN_DIM  1024

// Batch-independent synapse gain s[o,i] = d + a*sigmoid(dx*(w-x0)).
// __device__ global scratch (no runtime allocation allowed).
__device__ float g_s[OUT_DIM * IN_DIM];

__global__ void prep_kernel(const float* __restrict__ w,
                            const float* __restrict__ x0,
                            const float* __restrict__ dx,
                            const float* __restrict__ a,
                            const float* __restrict__ d) {
    int idx = blockIdx.x * blockDim.x + threadIdx.x;  // exactly 1M threads
    float z = dx[idx] * (w[idx] - x0[idx]);
    // numerically stable sigmoid, accurate to ~2 ulp of true value
    float e = expf(-fabsf(z));
    float t = 1.0f / (1.0f + e);
    float sig = (z >= 0.0f) ? t : e * t;
    g_s[idx] = d[idx] + a[idx] * sig;
}

// 20-round threefry-2x32 with key (0, 42) = jax.random.key(42).
// Returns x0 ^ x1 (the 32-bit fold used by JAX's partitionable random_bits).
__device__ __forceinline__ unsigned int tf20_xor(unsigned int x0, unsigned int x1) {
    const unsigned int K1 = 42u;
    const unsigned int K2 = 0x1BD11BDAu ^ 42u;  // 0x1BD11BF0
#define TFR(r) { x0 += x1; x1 = __funnelshift_l(x1, x1, (r)); x1 ^= x0; }
    // initial key injection: x0 += K0 (=0, elided); x1 += K1
    x1 += K1;
    TFR(13) TFR(15) TFR(26) TFR(6)    x0 += K1;  x1 += K2 + 1u;
    TFR(17) TFR(29) TFR(16) TFR(24)   x0 += K2;  x1 += 0u + 2u;
    TFR(13) TFR(15) TFR(26) TFR(6)    /*x0+=0*/  x1 += K1 + 3u;
    TFR(17) TFR(29) TFR(16) TFR(24)   x0 += K1;  x1 += K2 + 4u;
    TFR(13) TFR(15) TFR(26) TFR(6)    x0 += K2;  x1 += 0u + 5u;
#undef TFR
    return x0 ^ x1;
}

// One warp per output element (b, o). 8 warps/block share batch row b.
// lane handles 8 float4 chunks (32 samples): i = (k*32 + lane)*4 + c.
__global__ void __launch_bounds__(256)
synapse_kernel(const float* __restrict__ input,
               const float* __restrict__ bias,
               float* __restrict__ out) {
    const int warp = threadIdx.x >> 5;
    const int lane = threadIdx.x & 31;
    const int b = blockIdx.x >> 7;                    // 0..127
    const int o = ((blockIdx.x & 127) << 3) + warp;   // 0..1023

    const float bo = bias[o];   // hoisted; latency hidden under first chains

    const float4* __restrict__ inrow =
        reinterpret_cast<const float4*>(input + b * IN_DIM);
    const float4* __restrict__ srow =
        reinterpret_cast<const float4*>(g_s + o * IN_DIM);

    const unsigned int jbase = ((unsigned int)(b * OUT_DIM + o)) << 10;  // flat * IN_DIM

    int cnt = 0;
#pragma unroll 2
    for (int k = 0; k < 8; ++k) {
        const int v = (k << 5) + lane;      // float4 index within row, 0..255
        const float4 s4 = srow[v];
        const float4 x4 = inrow[v];
        const unsigned int j = jbase + ((unsigned int)v << 2);

        {
            float p = __saturatef(x4.x * s4.x);
            unsigned int y = tf20_xor(0u, j + 0u);
            float u = __uint_as_float((y >> 9) | 0x3f800000u) - 1.0f;
            cnt += (u < p);
        }
        {
            float p = __saturatef(x4.y * s4.y);
            unsigned int y = tf20_xor(0u, j + 1u);
            float u = __uint_as_float((y >> 9) | 0x3f800000u) - 1.0f;
            cnt += (u < p);
        }
        {
            float p = __saturatef(x4.z * s4.z);
            unsigned int y = tf20_xor(0u, j + 2u);
            float u = __uint_as_float((y >> 9) | 0x3f800000u) - 1.0f;
            cnt += (u < p);
        }
        {
            float p = __saturatef(x4.w * s4.w);
            unsigned int y = tf20_xor(0u, j + 3u);
            float u = __uint_as_float((y >> 9) | 0x3f800000u) - 1.0f;
            cnt += (u < p);
        }
    }

    // warp-level sum of the 32 partial counts
#pragma unroll
    for (int off = 16; off; off >>= 1)
        cnt += __shfl_xor_sync(0xffffffffu, cnt, off);

    if (lane == 0)
        out[b * OUT_DIM + o] = (float)cnt + bo;
}

extern "C" void kernel_launch(void* const* d_in, const int* in_sizes, int n_in,
                              void* d_out, int out_size) {
    const float* input  = (const float*)d_in[0];
    const float* weight = (const float*)d_in[1];
    const float* bias   = (const float*)d_in[2];
    const float* x0     = (const float*)d_in[3];
    const float* dx     = (const float*)d_in[4];
    const float* a      = (const float*)d_in[5];
    const float* d      = (const float*)d_in[6];
    float* out = (float*)d_out;

    // s[o,i] precompute: 1M elements
    prep_kernel<<<(OUT_DIM * IN_DIM) / 256, 256>>>(weight, x0, dx, a, d);

    // main: 128 b * 128 o-groups blocks, 8 warps/block (one (b,o) per warp)
    synapse_kernel<<<B_DIM * (OUT_DIM / 8), 256>>>(input, bias, out);
}